// round 5
// baseline (speedup 1.0000x reference)
#include <cuda_runtime.h>
#include <cuda_fp16.h>

#define D_FEAT 64
#define MAX_NODES 100000

// Scratch (static __device__ arrays -- no allocation).
__device__ int     g_row_ptr[MAX_NODES + 1];
__device__ __half2 g_x16[MAX_NODES * 32];   // fp16 copy of x: 100K rows x 64 feats = 12.8 MB

// Build row_ptr from the sorted target index: row_ptr[v] = first edge e with
// tgt[e] >= v. Boundary ranges are disjoint across e -> race-free writes.
__global__ void build_row_ptr_kernel(const int* __restrict__ tgt,
                                     int n_edges, int n_nodes) {
    const int e = blockIdx.x * blockDim.x + threadIdx.x;
    if (e >= n_edges) return;
    const int cur  = __ldg(tgt + e);
    const int prev = (e == 0) ? -1 : __ldg(tgt + e - 1);
    for (int v = prev + 1; v <= cur; ++v) g_row_ptr[v] = e;
    if (e == n_edges - 1) {
        for (int v = cur + 1; v <= n_nodes; ++v) g_row_ptr[v] = n_edges;
    }
}

// Streaming conversion: x (f32) -> g_x16 (fp16). One float4 per thread.
__global__ __launch_bounds__(256) void convert_x_kernel(
    const float4* __restrict__ xf4, int n_f4) {
    const int i = blockIdx.x * blockDim.x + threadIdx.x;
    if (i >= n_f4) return;
    const float4 v = __ldg(xf4 + i);
    __half2 h0 = __floats2half2_rn(v.x, v.y);
    __half2 h1 = __floats2half2_rn(v.z, v.w);
    g_x16[(size_t)i * 2 + 0] = h0;
    g_x16[(size_t)i * 2 + 1] = h1;
}

// One warp per output node (round-2 structure). Half-warp h serves edges with
// parity h; lane owns 4 features. Gathers read the fp16 copy: 8B per lane,
// 128B per row -> half the L1/L2 traffic of the f32 version. f32 accumulate.
__global__ __launch_bounds__(256) void mp_gather_kernel(
    const float* __restrict__ ev,   // [n_edges]
    const int*   __restrict__ src,  // [n_edges]
    float*       __restrict__ out,  // [n_nodes, 64]
    int n_nodes)
{
    const int warp = (blockIdx.x * blockDim.x + threadIdx.x) >> 5;
    if (warp >= n_nodes) return;
    const int lane = threadIdx.x & 31;
    const int half = lane >> 4;
    const int hl   = lane & 15;
    const int node = warp;

    const int start = __ldg(&g_row_ptr[node]);
    const int end   = __ldg(&g_row_ptr[node + 1]);

    // Row = 64 halves = 16 uint2 (8B each); lane hl reads uint2 #hl.
    const uint2* __restrict__ xh = (const uint2*)g_x16;
    float4 acc = make_float4(0.f, 0.f, 0.f, 0.f);

    for (int base = start; base < end; base += 32) {
        const int cnt = min(32, end - base);
        // Cooperative metadata load: lane l owns edge base+l of this batch.
        int   s_l = 0;
        float w_l = 0.f;
        if (lane < cnt) {
            s_l = __ldg(src + base + lane);
            w_l = __ldg(ev  + base + lane);
        }
        const int iters = (cnt + 1) >> 1;
        #pragma unroll 2
        for (int k = 0; k < iters; ++k) {
            const int j  = 2 * k + half;
            const int jj = min(j, cnt - 1);           // keep shfl convergent
            const int   s = __shfl_sync(0xffffffffu, s_l, jj);
            float       w = __shfl_sync(0xffffffffu, w_l, jj);
            if (j >= cnt) w = 0.f;                    // padded edge adds zero
            const uint2 raw = __ldg(&xh[(size_t)s * 16 + hl]);
            __half2 h0, h1;
            h0 = *reinterpret_cast<const __half2*>(&raw.x);
            h1 = *reinterpret_cast<const __half2*>(&raw.y);
            const float2 f0 = __half22float2(h0);
            const float2 f1 = __half22float2(h1);
            acc.x = fmaf(w, f0.x, acc.x);
            acc.y = fmaf(w, f0.y, acc.y);
            acc.z = fmaf(w, f1.x, acc.z);
            acc.w = fmaf(w, f1.y, acc.w);
        }
    }

    // Combine the two half-warp partial sums.
    acc.x += __shfl_xor_sync(0xffffffffu, acc.x, 16);
    acc.y += __shfl_xor_sync(0xffffffffu, acc.y, 16);
    acc.z += __shfl_xor_sync(0xffffffffu, acc.z, 16);
    acc.w += __shfl_xor_sync(0xffffffffu, acc.w, 16);

    if (half == 0) {
        float4* __restrict__ of4 = (float4*)out;
        of4[(size_t)node * 16 + hl] = acc;  // 256B coalesced store
    }
}

extern "C" void kernel_launch(void* const* d_in, const int* in_sizes, int n_in,
                              void* d_out, int out_size) {
    const float* x   = (const float*)d_in[0];
    const float* ev  = (const float*)d_in[1];
    const int*   tgt = (const int*)d_in[2];
    const int*   src = (const int*)d_in[3];
    float* out = (float*)d_out;

    const int n_edges = in_sizes[1];
    const int n_nodes = out_size / D_FEAT;
    const int n_f4    = n_nodes * (D_FEAT / 4);

    {
        const int threads = 256;
        convert_x_kernel<<<(n_f4 + threads - 1) / threads, threads>>>(
            (const float4*)x, n_f4);
    }
    {
        const int threads = 256;
        build_row_ptr_kernel<<<(n_edges + threads - 1) / threads, threads>>>(
            tgt, n_edges, n_nodes);
    }
    {
        const int threads = 256;
        const int blocks  = (n_nodes * 32 + threads - 1) / threads;
        mp_gather_kernel<<<blocks, threads>>>(ev, src, out, n_nodes);
    }
}

// round 6
// speedup vs baseline: 1.0342x; 1.0342x over previous
#include <cuda_runtime.h>
#include <cuda_fp16.h>

#define D_FEAT 64
#define MAX_NODES 100000

// Scratch (static __device__ arrays -- no allocation).
__device__ int   g_row_ptr[MAX_NODES + 1];
__device__ uint4 g_x16[MAX_NODES * 8];   // fp16 rows: 128B = 8 x uint4 per row

// Fused prep: blocks [0, rp_blocks) build row_ptr from the sorted targets;
// remaining blocks convert x (f32) -> g_x16 (fp16), 4 float4s per thread.
__global__ __launch_bounds__(256) void prep_kernel(
    const float4* __restrict__ xf4, int n_f4,
    const int* __restrict__ tgt, int n_edges, int n_nodes, int rp_blocks)
{
    if ((int)blockIdx.x < rp_blocks) {
        const int e = blockIdx.x * 256 + threadIdx.x;
        if (e >= n_edges) return;
        const int cur  = __ldg(tgt + e);
        const int prev = (e == 0) ? -1 : __ldg(tgt + e - 1);
        for (int v = prev + 1; v <= cur; ++v) g_row_ptr[v] = e;
        if (e == n_edges - 1) {
            for (int v = cur + 1; v <= n_nodes; ++v) g_row_ptr[v] = n_edges;
        }
    } else {
        const int r   = (blockIdx.x - rp_blocks) * 256 + threadIdx.x;
        const int idx = r * 4;                       // first float4 of this thread
        if (idx >= n_f4) return;
        const float4 a = __ldg(xf4 + idx + 0);
        const float4 b = __ldg(xf4 + idx + 1);
        const float4 c = __ldg(xf4 + idx + 2);
        const float4 d = __ldg(xf4 + idx + 3);
        __half2 h0 = __floats2half2_rn(a.x, a.y), h1 = __floats2half2_rn(a.z, a.w);
        __half2 h2 = __floats2half2_rn(b.x, b.y), h3 = __floats2half2_rn(b.z, b.w);
        __half2 h4 = __floats2half2_rn(c.x, c.y), h5 = __floats2half2_rn(c.z, c.w);
        __half2 h6 = __floats2half2_rn(d.x, d.y), h7 = __floats2half2_rn(d.z, d.w);
        uint4 o0, o1;
        o0.x = *reinterpret_cast<unsigned int*>(&h0);
        o0.y = *reinterpret_cast<unsigned int*>(&h1);
        o0.z = *reinterpret_cast<unsigned int*>(&h2);
        o0.w = *reinterpret_cast<unsigned int*>(&h3);
        o1.x = *reinterpret_cast<unsigned int*>(&h4);
        o1.y = *reinterpret_cast<unsigned int*>(&h5);
        o1.z = *reinterpret_cast<unsigned int*>(&h6);
        o1.w = *reinterpret_cast<unsigned int*>(&h7);
        g_x16[(size_t)r * 2 + 0] = o0;
        g_x16[(size_t)r * 2 + 1] = o1;
    }
}

// One warp per output node. Quarter-warp q = lane>>3 serves edges with index
// parity q (mod 4); lane owns 8 features as one uint4 (8 fp16) -> a full
// 128B fp16 row is one LDG.128 per 8-lane quarter. 4 edges in flight per
// iteration, unroll 2 -> 8 gathers in flight per warp. f32 accumulation.
__global__ __launch_bounds__(256) void mp_gather_kernel(
    const float* __restrict__ ev,   // [n_edges]
    const int*   __restrict__ src,  // [n_edges]
    float*       __restrict__ out,  // [n_nodes, 64]
    int n_nodes)
{
    const int warp = (blockIdx.x * blockDim.x + threadIdx.x) >> 5;
    if (warp >= n_nodes) return;
    const int lane = threadIdx.x & 31;
    const int q    = lane >> 3;   // edge parity (0..3)
    const int ql   = lane & 7;    // feature chunk (8 features each)
    const int node = warp;

    const int start = __ldg(&g_row_ptr[node]);
    const int end   = __ldg(&g_row_ptr[node + 1]);

    const uint4* __restrict__ xh = g_x16;   // row = 8 uint4
    float acc0 = 0.f, acc1 = 0.f, acc2 = 0.f, acc3 = 0.f;
    float acc4 = 0.f, acc5 = 0.f, acc6 = 0.f, acc7 = 0.f;

    for (int base = start; base < end; base += 32) {
        const int cnt = min(32, end - base);
        // Cooperative metadata load: lane l owns edge base+l of this batch.
        int   s_l = 0;
        float w_l = 0.f;
        if (lane < cnt) {
            s_l = __ldg(src + base + lane);
            w_l = __ldg(ev  + base + lane);
        }
        const int iters = (cnt + 3) >> 2;
        #pragma unroll 2
        for (int k = 0; k < iters; ++k) {
            const int j  = 4 * k + q;
            const int jj = min(j, cnt - 1);           // keep shfl convergent
            const int   s = __shfl_sync(0xffffffffu, s_l, jj);
            float       w = __shfl_sync(0xffffffffu, w_l, jj);
            if (j >= cnt) w = 0.f;                    // padded edge adds zero
            const uint4 raw = __ldg(&xh[(size_t)s * 8 + ql]);
            const __half2 p0 = *reinterpret_cast<const __half2*>(&raw.x);
            const __half2 p1 = *reinterpret_cast<const __half2*>(&raw.y);
            const __half2 p2 = *reinterpret_cast<const __half2*>(&raw.z);
            const __half2 p3 = *reinterpret_cast<const __half2*>(&raw.w);
            const float2 f0 = __half22float2(p0);
            const float2 f1 = __half22float2(p1);
            const float2 f2 = __half22float2(p2);
            const float2 f3 = __half22float2(p3);
            acc0 = fmaf(w, f0.x, acc0); acc1 = fmaf(w, f0.y, acc1);
            acc2 = fmaf(w, f1.x, acc2); acc3 = fmaf(w, f1.y, acc3);
            acc4 = fmaf(w, f2.x, acc4); acc5 = fmaf(w, f2.y, acc5);
            acc6 = fmaf(w, f3.x, acc6); acc7 = fmaf(w, f3.y, acc7);
        }
    }

    // Reduce across the 4 quarter-warps (lanes ql, 8+ql, 16+ql, 24+ql).
    acc0 += __shfl_xor_sync(0xffffffffu, acc0, 8);
    acc1 += __shfl_xor_sync(0xffffffffu, acc1, 8);
    acc2 += __shfl_xor_sync(0xffffffffu, acc2, 8);
    acc3 += __shfl_xor_sync(0xffffffffu, acc3, 8);
    acc4 += __shfl_xor_sync(0xffffffffu, acc4, 8);
    acc5 += __shfl_xor_sync(0xffffffffu, acc5, 8);
    acc6 += __shfl_xor_sync(0xffffffffu, acc6, 8);
    acc7 += __shfl_xor_sync(0xffffffffu, acc7, 8);
    acc0 += __shfl_xor_sync(0xffffffffu, acc0, 16);
    acc1 += __shfl_xor_sync(0xffffffffu, acc1, 16);
    acc2 += __shfl_xor_sync(0xffffffffu, acc2, 16);
    acc3 += __shfl_xor_sync(0xffffffffu, acc3, 16);
    acc4 += __shfl_xor_sync(0xffffffffu, acc4, 16);
    acc5 += __shfl_xor_sync(0xffffffffu, acc5, 16);
    acc6 += __shfl_xor_sync(0xffffffffu, acc6, 16);
    acc7 += __shfl_xor_sync(0xffffffffu, acc7, 16);

    if (q == 0) {  // lanes 0..7 hold the full sums for features [8ql, 8ql+8)
        float4* __restrict__ of4 = (float4*)out;
        of4[(size_t)node * 16 + 2 * ql + 0] = make_float4(acc0, acc1, acc2, acc3);
        of4[(size_t)node * 16 + 2 * ql + 1] = make_float4(acc4, acc5, acc6, acc7);
    }
}

extern "C" void kernel_launch(void* const* d_in, const int* in_sizes, int n_in,
                              void* d_out, int out_size) {
    const float* x   = (const float*)d_in[0];
    const float* ev  = (const float*)d_in[1];
    const int*   tgt = (const int*)d_in[2];
    const int*   src = (const int*)d_in[3];
    float* out = (float*)d_out;

    const int n_edges = in_sizes[1];
    const int n_nodes = out_size / D_FEAT;
    const int n_f4    = n_nodes * (D_FEAT / 4);

    const int rp_blocks = (n_edges + 255) / 256;
    const int cv_blocks = (n_f4 / 4 + 255) / 256;
    prep_kernel<<<rp_blocks + cv_blocks, 256>>>(
        (const float4*)x, n_f4, tgt, n_edges, n_nodes, rp_blocks);

    const int blocks = (n_nodes * 32 + 255) / 256;
    mp_gather_kernel<<<blocks, 256>>>(ev, src, out, n_nodes);
}

// round 7
// speedup vs baseline: 1.1930x; 1.1535x over previous
#include <cuda_runtime.h>
#include <cuda_fp16.h>

#define D_FEAT 64
#define MAX_NODES 100000

// Scratch (static __device__ arrays -- no allocation).
__device__ int   g_row_ptr[MAX_NODES + 1];
__device__ uint2 g_x16[MAX_NODES * 16];   // fp16 rows: 128B = 16 x uint2 per row

// Fused prep: blocks [0, rp_blocks) build row_ptr from the sorted targets;
// remaining blocks convert x (f32) -> g_x16 (fp16), 4 float4s per thread.
__global__ __launch_bounds__(256) void prep_kernel(
    const float4* __restrict__ xf4, int n_f4,
    const int* __restrict__ tgt, int n_edges, int n_nodes, int rp_blocks)
{
    if ((int)blockIdx.x < rp_blocks) {
        const int e = blockIdx.x * 256 + threadIdx.x;
        if (e >= n_edges) return;
        const int cur  = __ldg(tgt + e);
        const int prev = (e == 0) ? -1 : __ldg(tgt + e - 1);
        for (int v = prev + 1; v <= cur; ++v) g_row_ptr[v] = e;
        if (e == n_edges - 1) {
            for (int v = cur + 1; v <= n_nodes; ++v) g_row_ptr[v] = n_edges;
        }
    } else {
        const int r   = (blockIdx.x - rp_blocks) * 256 + threadIdx.x;
        const int idx = r * 4;                       // first float4 of this thread
        if (idx >= n_f4) return;
        const float4 a = __ldg(xf4 + idx + 0);
        const float4 b = __ldg(xf4 + idx + 1);
        const float4 c = __ldg(xf4 + idx + 2);
        const float4 d = __ldg(xf4 + idx + 3);
        __half2 h0 = __floats2half2_rn(a.x, a.y), h1 = __floats2half2_rn(a.z, a.w);
        __half2 h2 = __floats2half2_rn(b.x, b.y), h3 = __floats2half2_rn(b.z, b.w);
        __half2 h4 = __floats2half2_rn(c.x, c.y), h5 = __floats2half2_rn(c.z, c.w);
        __half2 h6 = __floats2half2_rn(d.x, d.y), h7 = __floats2half2_rn(d.z, d.w);
        uint4 o0, o1;
        o0.x = *reinterpret_cast<unsigned int*>(&h0);
        o0.y = *reinterpret_cast<unsigned int*>(&h1);
        o0.z = *reinterpret_cast<unsigned int*>(&h2);
        o0.w = *reinterpret_cast<unsigned int*>(&h3);
        o1.x = *reinterpret_cast<unsigned int*>(&h4);
        o1.y = *reinterpret_cast<unsigned int*>(&h5);
        o1.z = *reinterpret_cast<unsigned int*>(&h6);
        o1.w = *reinterpret_cast<unsigned int*>(&h7);
        ((uint4*)g_x16)[(size_t)r * 2 + 0] = o0;
        ((uint4*)g_x16)[(size_t)r * 2 + 1] = o1;
    }
}

__device__ __forceinline__ void fma_edge(float& a0, float& a1, float& a2, float& a3,
                                         float w, uint2 raw) {
    const float2 f0 = __half22float2(*reinterpret_cast<const __half2*>(&raw.x));
    const float2 f1 = __half22float2(*reinterpret_cast<const __half2*>(&raw.y));
    a0 = fmaf(w, f0.x, a0);
    a1 = fmaf(w, f0.y, a1);
    a2 = fmaf(w, f1.x, a2);
    a3 = fmaf(w, f1.y, a3);
}

// One warp per output node. Half-warp h serves edges of parity h; lane owns
// 4 features as one uint2 (4 fp16). Main loop: 4 edge-pairs per step => 4
// independent uint2 gathers in flight per lane (8 edges/warp), only 8 regs
// of load temps -> keeps regs ~32-36 and occupancy high. f32 accumulate.
__global__ __launch_bounds__(128) void mp_gather_kernel(
    const float* __restrict__ ev,   // [n_edges]
    const int*   __restrict__ src,  // [n_edges]
    float*       __restrict__ out,  // [n_nodes, 64]
    int n_nodes)
{
    const int warp = (blockIdx.x * blockDim.x + threadIdx.x) >> 5;
    if (warp >= n_nodes) return;
    const int lane = threadIdx.x & 31;
    const int half = lane >> 4;
    const int hl   = lane & 15;
    const int node = warp;

    const int start = __ldg(&g_row_ptr[node]);
    const int end   = __ldg(&g_row_ptr[node + 1]);

    const uint2* __restrict__ xh = g_x16;   // row = 16 uint2
    float a0 = 0.f, a1 = 0.f, a2 = 0.f, a3 = 0.f;

    for (int base = start; base < end; base += 32) {
        const int cnt = min(32, end - base);
        // Cooperative metadata load: lane l owns edge base+l of this batch.
        int   s_l = 0;
        float w_l = 0.f;
        if (lane < cnt) {
            s_l = __ldg(src + base + lane);
            w_l = __ldg(ev  + base + lane);
        }

        const int full = cnt >> 1;   // complete pairs (both parities valid)
        int k = 0;

        // Main path: 4 pairs per step -> 4 independent gathers per lane.
        for (; k + 4 <= full; k += 4) {
            const int j0 = 2 * (k + 0) + half;
            const int j1 = 2 * (k + 1) + half;
            const int j2 = 2 * (k + 2) + half;
            const int j3 = 2 * (k + 3) + half;
            const int s0 = __shfl_sync(0xffffffffu, s_l, j0);
            const int s1 = __shfl_sync(0xffffffffu, s_l, j1);
            const int s2 = __shfl_sync(0xffffffffu, s_l, j2);
            const int s3 = __shfl_sync(0xffffffffu, s_l, j3);
            const uint2 r0 = __ldg(&xh[(size_t)s0 * 16 + hl]);
            const uint2 r1 = __ldg(&xh[(size_t)s1 * 16 + hl]);
            const uint2 r2 = __ldg(&xh[(size_t)s2 * 16 + hl]);
            const uint2 r3 = __ldg(&xh[(size_t)s3 * 16 + hl]);
            const float w0 = __shfl_sync(0xffffffffu, w_l, j0);
            const float w1 = __shfl_sync(0xffffffffu, w_l, j1);
            const float w2 = __shfl_sync(0xffffffffu, w_l, j2);
            const float w3 = __shfl_sync(0xffffffffu, w_l, j3);
            fma_edge(a0, a1, a2, a3, w0, r0);
            fma_edge(a0, a1, a2, a3, w1, r1);
            fma_edge(a0, a1, a2, a3, w2, r2);
            fma_edge(a0, a1, a2, a3, w3, r3);
        }
        // Remaining complete pairs.
        for (; k < full; ++k) {
            const int j = 2 * k + half;
            const int   s = __shfl_sync(0xffffffffu, s_l, j);
            const float w = __shfl_sync(0xffffffffu, w_l, j);
            const uint2 r = __ldg(&xh[(size_t)s * 16 + hl]);
            fma_edge(a0, a1, a2, a3, w, r);
        }
        // Odd trailing edge: half 1 contributes zero (load still valid).
        if (cnt & 1) {
            const int j = cnt - 1;
            const int   s = __shfl_sync(0xffffffffu, s_l, j);
            float       w = __shfl_sync(0xffffffffu, w_l, j);
            if (half) w = 0.f;
            const uint2 r = __ldg(&xh[(size_t)s * 16 + hl]);
            fma_edge(a0, a1, a2, a3, w, r);
        }
    }

    // Combine the two half-warp partial sums.
    a0 += __shfl_xor_sync(0xffffffffu, a0, 16);
    a1 += __shfl_xor_sync(0xffffffffu, a1, 16);
    a2 += __shfl_xor_sync(0xffffffffu, a2, 16);
    a3 += __shfl_xor_sync(0xffffffffu, a3, 16);

    if (half == 0) {
        float4* __restrict__ of4 = (float4*)out;
        of4[(size_t)node * 16 + hl] = make_float4(a0, a1, a2, a3);
    }
}

extern "C" void kernel_launch(void* const* d_in, const int* in_sizes, int n_in,
                              void* d_out, int out_size) {
    const float* x   = (const float*)d_in[0];
    const float* ev  = (const float*)d_in[1];
    const int*   tgt = (const int*)d_in[2];
    const int*   src = (const int*)d_in[3];
    float* out = (float*)d_out;

    const int n_edges = in_sizes[1];
    const int n_nodes = out_size / D_FEAT;
    const int n_f4    = n_nodes * (D_FEAT / 4);

    const int rp_blocks = (n_edges + 255) / 256;
    const int cv_blocks = (n_f4 / 4 + 255) / 256;
    prep_kernel<<<rp_blocks + cv_blocks, 256>>>(
        (const float4*)x, n_f4, tgt, n_edges, n_nodes, rp_blocks);

    const int threads = 128;  // 4 warps/block: less block-retire imbalance
    const int blocks  = (n_nodes * 32 + threads - 1) / threads;
    mp_gather_kernel<<<blocks, threads>>>(ev, src, out, n_nodes);
}